// round 15
// baseline (speedup 1.0000x reference)
#include <cuda_runtime.h>
#include <math.h>

// ---------------- problem constants ----------------
#define BATCH 4
#define CIN   64
#define CMOD  128          // d_model
#define HW    64           // output spatial side
#define L     4096         // HW*HW
#define M_TOT (BATCH*L)    // 16384 token rows
#define DIN   256          // d_inner
#define DST   16           // d_state
#define DTR   8            // dt_rank
#define NC    32           // scan chunks
#define LC    128          // chunk length (NC*LC == L)
#define NL    (BATCH*DIN*DST)   // 16384 scan lanes
#define LP    132          // padded l-stride for transposed smem

typedef unsigned long long ull;

// ---------------- scratch (device globals; no allocs allowed) ----------------
__device__ float g_y   [BATCH * CMOD * L];   // gelu(bn(conv)) in [b][c][l]
__device__ float g_xz  [M_TOT * 2 * DIN];    // in-proj output [m][512]
__device__ float g_bc  [M_TOT * 32];         // [m][32] : B(16) | C(16)
__device__ float g_del [M_TOT * DIN];        // delta[m][d]
__device__ float g_du  [M_TOT * DIN];        // delta*xin
__device__ float g_xd  [M_TOT * DIN];        // xin*Dp
__device__ float g_yg  [M_TOT * DIN];        // gated scan output [m][256]
__device__ float g_q   [NC * NL];            // [ch][lane] chunk local final state
__device__ float g_ap  [NC * NL];            // [ch][lane] chunk decay aggregate
__device__ float g_hin [NC * NL];            // [ch][lane] state entering chunk

// ---------------- helpers ----------------
__device__ __forceinline__ float silu_f(float v){ return v / (1.f + __expf(-v)); }
__device__ __forceinline__ float softplus_f(float v){ return (v > 20.f) ? v : log1pf(__expf(v)); }
__device__ __forceinline__ float gelu_f(float v){ return 0.5f * v * (1.f + erff(v * 0.70710678118654752f)); }

__device__ __forceinline__ ull pack2(float lo, float hi){
    ull r; asm("mov.b64 %0, {%1, %2};" : "=l"(r) : "f"(lo), "f"(hi)); return r;
}
__device__ __forceinline__ void ffma2(ull& d, ull a, ull b){
    asm("fma.rn.f32x2 %0, %1, %2, %0;" : "+l"(d) : "l"(a), "l"(b));
}
__device__ __forceinline__ float2 unpack2(ull v){
    float2 r; asm("mov.b64 {%0, %1}, %2;" : "=f"(r.x), "=f"(r.y) : "l"(v)); return r;
}

// =====================================================================
// K1: conv3x3 stride2 pad1 (64->128ch) + bias + BN(eval) + exact GELU
// v5: 4 input channels per chunk (16 chunks, 32 barriers total)
// tile 16x16 outputs, 256 threads (1 output x 16 oc), halo 33x33
// grid (16 spatial, 8 oc, 4 b) = 512 blocks
// =====================================================================
#define HALO (33*33)
#define HALO4 (4*HALO)     // 4356 floats per chunk

__global__ void __launch_bounds__(256, 3)
k_conv(const float* __restrict__ x, const float* __restrict__ w,
       const float* __restrict__ cb, const float* __restrict__ bng,
       const float* __restrict__ bnb, const float* __restrict__ bnm,
       const float* __restrict__ bnv)
{
    __shared__ float in_s[HALO4];            // 4 ci x 33x33 halo (17.4 KB)
    __shared__ __align__(16) float w_s[4 * 9 * 16];   // 576 floats

    const int t  = threadIdx.x;              // 0..255
    const int tx = t & 15;                   // col 0..15
    const int ty = t >> 4;                   // row 0..15
    const int bx = blockIdx.x;
    const int oh0 = (bx >> 2) * 16, ow0 = (bx & 3) * 16;
    const int oc0 = blockIdx.y * 16;
    const int b   = blockIdx.z;
    const int ih0 = oh0 * 2 - 1, iw0 = ow0 * 2 - 1;

    ull acc2[8];
    #pragma unroll
    for (int o = 0; o < 8; o++) acc2[o] = 0ull;

    for (int cc = 0; cc < CIN; cc += 4) {
        __syncthreads();
        for (int idx = t; idx < HALO4; idx += 256) {
            int ci = idx / HALO, rem = idx - ci * HALO;
            int r = rem / 33, cl = rem - r * 33;
            int ih = ih0 + r, iw = iw0 + cl;
            float v = 0.f;
            if (ih >= 0 && ih < 128 && iw >= 0 && iw < 128)
                v = x[((b * CIN + cc + ci) * 128 + ih) * 128 + iw];
            in_s[idx] = v;
        }
        for (int idx = t; idx < 576; idx += 256) {
            int oc = idx & 15, rk = idx >> 4;    // rk = ci*9 + k, 0..35
            int ci = rk / 9, k = rk - ci * 9;
            w_s[idx] = w[(oc0 + oc) * (CIN * 9) + (cc + ci) * 9 + k];
        }
        __syncthreads();

        #pragma unroll
        for (int ci = 0; ci < 4; ci++)
            #pragma unroll
            for (int kh = 0; kh < 3; kh++) {
                const int r = 2 * ty + kh;
                #pragma unroll
                for (int kw = 0; kw < 3; kw++) {
                    const ull* wr2 = (const ull*)&w_s[(ci * 9 + kh * 3 + kw) * 16];
                    float iv = in_s[ci * HALO + r * 33 + 2 * tx + kw];
                    ull iv2 = pack2(iv, iv);
                    #pragma unroll
                    for (int o = 0; o < 8; o++)
                        ffma2(acc2[o], iv2, wr2[o]);
                }
            }
    }

    const int oh = oh0 + ty, ow = ow0 + tx;
    #pragma unroll
    for (int o = 0; o < 8; o++) {
        float2 pv = unpack2(acc2[o]);
        #pragma unroll
        for (int half = 0; half < 2; half++) {
            int c = oc0 + o * 2 + half;
            float inv = bng[c] * rsqrtf(bnv[c] + 1e-5f);
            float v = ((half ? pv.y : pv.x) + cb[c] - bnm[c]) * inv + bnb[c];
            g_y[(b * CMOD + c) * L + oh * HW + ow] = gelu_f(v);
        }
    }
}

// =====================================================================
// K2: in-proj GEMM  xz[m][e] = sum_k y[b][k][l] * in_w[e][k]
// BM=128, BE=128, BK=16 single-buffered
// =====================================================================
__global__ void k_gemm_xz(const float* __restrict__ in_w)
{
    __shared__ __align__(16) float As[16][128];
    __shared__ __align__(16) float Bs[16][128];
    const int t  = threadIdx.x;
    const int tx = t & 15, ty = t >> 4;
    const int e0 = blockIdx.x * 128;
    const int m0 = blockIdx.y * 128;
    const int b  = m0 >> 12;
    const int l0 = m0 & 4095;

    const int arow4 = (t & 31) * 4;
    const int ak    = t >> 5;
    const int brow  = t >> 1;
    const int bkq   = (t & 1) * 4;

    ull acc2[8][4];
    #pragma unroll
    for (int i = 0; i < 8; i++)
        #pragma unroll
        for (int j = 0; j < 4; j++) acc2[i][j] = 0ull;

    for (int k0 = 0; k0 < CMOD; k0 += 16) {
        __syncthreads();
        {
            float4 a0 = *(const float4*)&g_y[(b * CMOD + k0 + ak) * L + l0 + arow4];
            float4 a1 = *(const float4*)&g_y[(b * CMOD + k0 + 8 + ak) * L + l0 + arow4];
            *(float4*)&As[ak][arow4] = a0;
            *(float4*)&As[ak + 8][arow4] = a1;
            float4 b0 = *(const float4*)&in_w[(e0 + brow) * CMOD + k0 + bkq];
            float4 b1 = *(const float4*)&in_w[(e0 + brow) * CMOD + k0 + bkq + 8];
            Bs[bkq + 0][brow] = b0.x; Bs[bkq + 1][brow] = b0.y;
            Bs[bkq + 2][brow] = b0.z; Bs[bkq + 3][brow] = b0.w;
            Bs[bkq + 8][brow] = b1.x; Bs[bkq + 9][brow] = b1.y;
            Bs[bkq +10][brow] = b1.z; Bs[bkq +11][brow] = b1.w;
        }
        __syncthreads();
        #pragma unroll
        for (int k = 0; k < 16; k++) {
            float a[8];
            *(float4*)&a[0] = *(float4*)&As[k][ty * 4];
            *(float4*)&a[4] = *(float4*)&As[k][ty * 4 + 64];
            ull b2[4];
            b2[0] = *(const ull*)&Bs[k][tx * 4];
            b2[1] = *(const ull*)&Bs[k][tx * 4 + 2];
            b2[2] = *(const ull*)&Bs[k][tx * 4 + 64];
            b2[3] = *(const ull*)&Bs[k][tx * 4 + 66];
            #pragma unroll
            for (int i = 0; i < 8; i++) {
                ull a2 = pack2(a[i], a[i]);
                #pragma unroll
                for (int j = 0; j < 4; j++)
                    ffma2(acc2[i][j], a2, b2[j]);
            }
        }
    }
    #pragma unroll
    for (int i = 0; i < 8; i++) {
        int m = m0 + ty * 4 + (i & 3) + (i >> 2) * 64;
        float2 p0 = unpack2(acc2[i][0]), p1 = unpack2(acc2[i][1]);
        float2 p2 = unpack2(acc2[i][2]), p3 = unpack2(acc2[i][3]);
        float4 v0 = make_float4(p0.x, p0.y, p1.x, p1.y);
        float4 v1 = make_float4(p2.x, p2.y, p3.x, p3.y);
        *(float4*)&g_xz[(size_t)m * 512 + e0 + tx * 4] = v0;
        *(float4*)&g_xz[(size_t)m * 512 + e0 + tx * 4 + 64] = v1;
    }
}

// =====================================================================
// K3: FUSED conv1d+SiLU + x-proj + delta/softplus + precompute
// =====================================================================
__global__ void k_cproj(const float* __restrict__ w, const float* __restrict__ bias,
                        const float* __restrict__ xpw, const float* __restrict__ dtw_g,
                        const float* __restrict__ dtb_g, const float* __restrict__ Dp_g)
{
    __shared__ float As[32 * 257];
    __shared__ float misc[2560];
    __shared__ float dt_sm[32][8];

    const int t  = threadIdx.x;
    const int m0 = blockIdx.x * 32;
    const int b  = m0 >> 12;
    const int l0 = m0 & 4095;

    {
        const int d = t;
        const float w0 = w[d * 4 + 0], w1 = w[d * 4 + 1], w2 = w[d * 4 + 2], w3 = w[d * 4 + 3];
        const float bs = bias[d];
        float xm3 = (l0 >= 3) ? g_xz[(size_t)(b * L + l0 - 3) * 512 + d] : 0.f;
        float xm2 = (l0 >= 2) ? g_xz[(size_t)(b * L + l0 - 2) * 512 + d] : 0.f;
        float xm1 = (l0 >= 1) ? g_xz[(size_t)(b * L + l0 - 1) * 512 + d] : 0.f;
        #pragma unroll 4
        for (int l = 0; l < 32; l++) {
            float xc = g_xz[(size_t)(b * L + l0 + l) * 512 + d];
            float v = fmaf(w0, xm3, fmaf(w1, xm2, fmaf(w2, xm1, fmaf(w3, xc, bs))));
            As[l * 257 + d] = silu_f(v);
            xm3 = xm2; xm2 = xm1; xm1 = xc;
        }
    }

    const int tx = t & 7;
    const int ty = t >> 3;
    float acc[5] = {0.f, 0.f, 0.f, 0.f, 0.f};

    for (int k0 = 0; k0 < 256; k0 += 32) {
        __syncthreads();
        for (int idx = t; idx < 320; idx += 256) {
            int e = idx >> 3, k4 = idx & 7;
            float4 v = *(const float4*)&xpw[e * 256 + k0 + k4 * 4];
            misc[(k4 * 4 + 0) * 41 + e] = v.x; misc[(k4 * 4 + 1) * 41 + e] = v.y;
            misc[(k4 * 4 + 2) * 41 + e] = v.z; misc[(k4 * 4 + 3) * 41 + e] = v.w;
        }
        __syncthreads();
        #pragma unroll
        for (int k = 0; k < 32; k++) {
            float a = As[ty * 257 + k0 + k];
            #pragma unroll
            for (int j = 0; j < 5; j++)
                acc[j] = fmaf(a, misc[k * 41 + tx * 5 + j], acc[j]);
        }
    }
    __syncthreads();

    #pragma unroll
    for (int j = 0; j < 5; j++) {
        int e = tx * 5 + j;
        if (e < 8) dt_sm[ty][e] = acc[j];
        else       g_bc[(size_t)(m0 + ty) * 32 + (e - 8)] = acc[j];
    }
    for (int idx = t; idx < 2048; idx += 256)
        misc[(idx & 7) * 256 + (idx >> 3)] = dtw_g[idx];
    misc[2048 + t] = dtb_g[t];
    misc[2304 + t] = Dp_g[t];
    __syncthreads();

    {
        const int d = t;
        float wv[8];
        #pragma unroll
        for (int r = 0; r < 8; r++) wv[r] = misc[r * 256 + d];
        const float dtbv = misc[2048 + d];
        const float Dpv  = misc[2304 + d];
        #pragma unroll 4
        for (int m = 0; m < 32; m++) {
            float s = dtbv;
            #pragma unroll
            for (int r = 0; r < 8; r++) s = fmaf(dt_sm[m][r], wv[r], s);
            float delta = softplus_f(s);
            float xv = As[m * 257 + d];
            size_t o = (size_t)(m0 + m) * 256 + d;
            g_del[o] = delta;
            g_du[o]  = delta * xv;
            g_xd[o]  = xv * Dpv;
        }
    }
}

// =====================================================================
// K5a: scan phase 1 — transposed l-major smem, float4 per 4 steps
// =====================================================================
__global__ void k_scan1(const float* __restrict__ A_log)
{
    __shared__ __align__(16) float del_t[8 * LP];
    __shared__ __align__(16) float du_t [8 * LP];
    __shared__ __align__(16) float B_t  [16 * LP];

    const int b  = blockIdx.z;
    const int ch = blockIdx.y;
    const int d0 = blockIdx.x * 8;
    const int t  = threadIdx.x;
    const int n  = t & 15, dl = t >> 4;
    const float A_dn = -__expf(A_log[(d0 + dl) * DST + n]);
    const int mb = b * L + ch * LC;

    #pragma unroll
    for (int j = 0; j < 2; j++) {
        int i4 = t + j * 128; int l = i4 >> 1, q = i4 & 1;
        float4 v = *(const float4*)&g_del[(size_t)(mb + l) * 256 + d0 + q * 4];
        del_t[(q * 4 + 0) * LP + l] = v.x; del_t[(q * 4 + 1) * LP + l] = v.y;
        del_t[(q * 4 + 2) * LP + l] = v.z; del_t[(q * 4 + 3) * LP + l] = v.w;
        float4 u = *(const float4*)&g_du[(size_t)(mb + l) * 256 + d0 + q * 4];
        du_t[(q * 4 + 0) * LP + l] = u.x; du_t[(q * 4 + 1) * LP + l] = u.y;
        du_t[(q * 4 + 2) * LP + l] = u.z; du_t[(q * 4 + 3) * LP + l] = u.w;
    }
    #pragma unroll
    for (int j = 0; j < 4; j++) {
        int i4 = t + j * 128; int l = i4 >> 2, q = i4 & 3;
        float4 v = *(const float4*)&g_bc[(size_t)(mb + l) * 32 + q * 4];
        B_t[(q * 4 + 0) * LP + l] = v.x; B_t[(q * 4 + 1) * LP + l] = v.y;
        B_t[(q * 4 + 2) * LP + l] = v.z; B_t[(q * 4 + 3) * LP + l] = v.w;
    }
    __syncthreads();

    float h = 0.f, sdel = 0.f;
    const float* dp = &del_t[dl * LP];
    const float* up = &du_t[dl * LP];
    const float* bp = &B_t[n * LP];
    #pragma unroll 4
    for (int l4 = 0; l4 < LC; l4 += 4) {
        float4 d4 = *(const float4*)&dp[l4];
        float4 u4 = *(const float4*)&up[l4];
        float4 b4 = *(const float4*)&bp[l4];
        h = fmaf(__expf(d4.x * A_dn), h, u4.x * b4.x);
        h = fmaf(__expf(d4.y * A_dn), h, u4.y * b4.y);
        h = fmaf(__expf(d4.z * A_dn), h, u4.z * b4.z);
        h = fmaf(__expf(d4.w * A_dn), h, u4.w * b4.w);
        sdel += (d4.x + d4.y) + (d4.z + d4.w);
    }
    const int lane = (b * DIN + d0) * DST + t;
    g_q [ch * NL + lane] = h;
    g_ap[ch * NL + lane] = __expf(A_dn * sdel);
}

// =====================================================================
// K5b: scan phase 2 — combine chunk aggregates
// =====================================================================
__global__ void k_scan2()
{
    const int lane = blockIdx.x * 128 + threadIdx.x;
    float h = 0.f;
    #pragma unroll
    for (int ch = 0; ch < NC; ch++) {
        g_hin[ch * NL + lane] = h;
        h = fmaf(g_ap[ch * NL + lane], h, g_q[ch * NL + lane]);
    }
}

// =====================================================================
// K5c: scan phase 3 — transposed staging + STS n-reduction + gate
// =====================================================================
__global__ void k_scan3(const float* __restrict__ A_log)
{
    __shared__ __align__(16) float del_t[8 * LP];
    __shared__ __align__(16) float du_t [8 * LP];
    __shared__ __align__(16) float B_t  [16 * LP];
    __shared__ __align__(16) float C_t  [16 * LP];
    __shared__ __align__(16) float ys_s [LC * 8];
    __shared__ float ysp[32 * 8 * 17];

    const int b  = blockIdx.z;
    const int ch = blockIdx.y;
    const int d0 = blockIdx.x * 8;
    const int t  = threadIdx.x;
    const int n  = t & 15, dl = t >> 4;
    const float A_dn = -__expf(A_log[(d0 + dl) * DST + n]);
    const int mb = b * L + ch * LC;

    #pragma unroll
    for (int j = 0; j < 2; j++) {
        int i4 = t + j * 128; int l = i4 >> 1, q = i4 & 1;
        float4 v = *(const float4*)&g_del[(size_t)(mb + l) * 256 + d0 + q * 4];
        del_t[(q * 4 + 0) * LP + l] = v.x; del_t[(q * 4 + 1) * LP + l] = v.y;
        del_t[(q * 4 + 2) * LP + l] = v.z; del_t[(q * 4 + 3) * LP + l] = v.w;
        float4 u = *(const float4*)&g_du[(size_t)(mb + l) * 256 + d0 + q * 4];
        du_t[(q * 4 + 0) * LP + l] = u.x; du_t[(q * 4 + 1) * LP + l] = u.y;
        du_t[(q * 4 + 2) * LP + l] = u.z; du_t[(q * 4 + 3) * LP + l] = u.w;
    }
    #pragma unroll
    for (int j = 0; j < 8; j++) {
        int i4 = t + j * 128; int l = i4 >> 3, q = i4 & 7;
        float4 v = *(const float4*)&g_bc[(size_t)(mb + l) * 32 + q * 4];
        float* dst = (q < 4) ? &B_t[(q * 4) * LP + l] : &C_t[((q - 4) * 4) * LP + l];
        dst[0 * LP] = v.x; dst[1 * LP] = v.y; dst[2 * LP] = v.z; dst[3 * LP] = v.w;
    }
    __syncthreads();

    const int lane = (b * DIN + d0) * DST + t;
    float h = g_hin[ch * NL + lane];
    const float* dp = &del_t[dl * LP];
    const float* up = &du_t[dl * LP];
    const float* bp = &B_t[n * LP];
    const float* cp = &C_t[n * LP];

    #pragma unroll
    for (int qq = 0; qq < 4; qq++) {
        #pragma unroll 4
        for (int li = 0; li < 32; li += 4) {
            int l = qq * 32 + li;
            float4 d4 = *(const float4*)&dp[l];
            float4 u4 = *(const float4*)&up[l];
            float4 b4 = *(const float4*)&bp[l];
            float4 c4 = *(const float4*)&cp[l];
            h = fmaf(__expf(d4.x * A_dn), h, u4.x * b4.x);
            ysp[((li + 0) * 8 + dl) * 17 + n] = h * c4.x;
            h = fmaf(__expf(d4.y * A_dn), h, u4.y * b4.y);
            ysp[((li + 1) * 8 + dl) * 17 + n] = h * c4.y;
            h = fmaf(__expf(d4.z * A_dn), h, u4.z * b4.z);
            ysp[((li + 2) * 8 + dl) * 17 + n] = h * c4.z;
            h = fmaf(__expf(d4.w * A_dn), h, u4.w * b4.w);
            ysp[((li + 3) * 8 + dl) * 17 + n] = h * c4.w;
        }
        __syncthreads();
        #pragma unroll
        for (int rep = 0; rep < 2; rep++) {
            int idx = t + rep * 128;
            int ll = idx >> 3, dd = idx & 7;
            float s = 0.f;
            #pragma unroll
            for (int nn = 0; nn < 16; nn++)
                s += ysp[(ll * 8 + dd) * 17 + nn];
            ys_s[(qq * 32 + ll) * 8 + dd] = s;
        }
        __syncthreads();
    }

    #pragma unroll
    for (int j = 0; j < 2; j++) {
        int i4 = t + j * 128; int l = i4 >> 1, q = i4 & 1;
        float4 z4 = *(const float4*)&g_xz[(size_t)(mb + l) * 512 + 256 + d0 + q * 4];
        float4 xd = *(const float4*)&g_xd[(size_t)(mb + l) * 256 + d0 + q * 4];
        float4 ys = *(const float4*)&ys_s[l * 8 + q * 4];
        float4 o;
        o.x = (ys.x + xd.x) * silu_f(z4.x);
        o.y = (ys.y + xd.y) * silu_f(z4.y);
        o.z = (ys.z + xd.z) * silu_f(z4.z);
        o.w = (ys.w + xd.w) * silu_f(z4.w);
        *(float4*)&g_yg[(size_t)(mb + l) * 256 + d0 + q * 4] = o;
    }
}

// =====================================================================
// K6: out-proj GEMM + residual, BK=16 single-buffered
// =====================================================================
__global__ void k_gemm_out(const float* __restrict__ ow, float* __restrict__ out)
{
    __shared__ __align__(16) float As[16][128];
    __shared__ __align__(16) float Bs[16][128];
    const int t  = threadIdx.x;
    const int tx = t & 15, ty = t >> 4;
    const int m0 = blockIdx.x * 128;
    const int b  = m0 >> 12;
    const int l0 = m0 & 4095;

    const int row = t >> 1;
    const int kq  = (t & 1) * 4;

    ull acc2[8][4];
    #pragma unroll
    for (int i = 0; i < 8; i++)
        #pragma unroll
        for (int j = 0; j < 4; j++) acc2[i][j] = 0ull;

    for (int k0 = 0; k0 < DIN; k0 += 16) {
        __syncthreads();
        {
            float4 a0 = *(const float4*)&g_yg[(size_t)(m0 + row) * DIN + k0 + kq];
            float4 a1 = *(const float4*)&g_yg[(size_t)(m0 + row) * DIN + k0 + kq + 8];
            As[kq + 0][row] = a0.x; As[kq + 1][row] = a0.y;
            As[kq + 2][row] = a0.z; As[kq + 3][row] = a0.w;
            As[kq + 8][row] = a1.x; As[kq + 9][row] = a1.y;
            As[kq +10][row] = a1.z; As[kq +11][row] = a1.w;
            float4 b0 = *(const float4*)&ow[row * DIN + k0 + kq];
            float4 b1 = *(const float4*)&ow[row * DIN + k0 + kq + 8];
            Bs[kq + 0][row] = b0.x; Bs[kq + 1][row] = b0.y;
            Bs[kq + 2][row] = b0.z; Bs[kq + 3][row] = b0.w;
            Bs[kq + 8][row] = b1.x; Bs[kq + 9][row] = b1.y;
            Bs[kq +10][row] = b1.z; Bs[kq +11][row] = b1.w;
        }
        __syncthreads();
        #pragma unroll
        for (int k = 0; k < 16; k++) {
            ull am2[4];
            am2[0] = *(const ull*)&As[k][tx * 4];
            am2[1] = *(const ull*)&As[k][tx * 4 + 2];
            am2[2] = *(const ull*)&As[k][tx * 4 + 64];
            am2[3] = *(const ull*)&As[k][tx * 4 + 66];
            float bc[8];
            *(float4*)&bc[0] = *(float4*)&Bs[k][ty * 4];
            *(float4*)&bc[4] = *(float4*)&Bs[k][ty * 4 + 64];
            #pragma unroll
            for (int ci = 0; ci < 8; ci++) {
                ull c2 = pack2(bc[ci], bc[ci]);
                #pragma unroll
                for (int mj = 0; mj < 4; mj++)
                    ffma2(acc2[ci][mj], c2, am2[mj]);
            }
        }
    }
    #pragma unroll
    for (int ci = 0; ci < 8; ci++) {
        int c = ty * 4 + (ci & 3) + (ci >> 2) * 64;
        size_t base = (size_t)(b * CMOD + c) * L + l0;
        float2 p0 = unpack2(acc2[ci][0]), p1 = unpack2(acc2[ci][1]);
        float2 p2 = unpack2(acc2[ci][2]), p3 = unpack2(acc2[ci][3]);
        float4 r0 = *(const float4*)&g_y[base + tx * 4];
        r0.x += p0.x; r0.y += p0.y; r0.z += p1.x; r0.w += p1.y;
        *(float4*)&out[base + tx * 4] = r0;
        float4 r1 = *(const float4*)&g_y[base + tx * 4 + 64];
        r1.x += p2.x; r1.y += p2.y; r1.z += p3.x; r1.w += p3.y;
        *(float4*)&out[base + tx * 4 + 64] = r1;
    }
}

// =====================================================================
extern "C" void kernel_launch(void* const* d_in, const int* in_sizes, int n_in,
                              void* d_out, int out_size)
{
    const float* x        = (const float*)d_in[0];
    const float* conv_w   = (const float*)d_in[1];
    const float* conv_b   = (const float*)d_in[2];
    const float* bn_g     = (const float*)d_in[3];
    const float* bn_b     = (const float*)d_in[4];
    const float* bn_mean  = (const float*)d_in[5];
    const float* bn_var   = (const float*)d_in[6];
    const float* in_w     = (const float*)d_in[7];
    const float* conv1d_w = (const float*)d_in[8];
    const float* conv1d_b = (const float*)d_in[9];
    const float* xproj_w  = (const float*)d_in[10];
    const float* dtproj_w = (const float*)d_in[11];
    const float* dtproj_b = (const float*)d_in[12];
    const float* A_log    = (const float*)d_in[13];
    const float* Dp       = (const float*)d_in[14];
    const float* out_w    = (const float*)d_in[15];
    float* out = (float*)d_out;

    k_conv    <<<dim3(16, 8, 4), 256>>>(x, conv_w, conv_b, bn_g, bn_b, bn_mean, bn_var);
    k_gemm_xz <<<dim3(4, 128), 256>>>(in_w);
    k_cproj   <<<512, 256>>>(conv1d_w, conv1d_b, xproj_w, dtproj_w, dtproj_b, Dp);
    k_scan1   <<<dim3(32, NC, 4), 128>>>(A_log);
    k_scan2   <<<128, 128>>>();
    k_scan3   <<<dim3(32, NC, 4), 128>>>(A_log);
    k_gemm_out<<<128, 256>>>(out_w, out);
}

// round 16
// speedup vs baseline: 1.0622x; 1.0622x over previous
#include <cuda_runtime.h>
#include <math.h>

// ---------------- problem constants ----------------
#define BATCH 4
#define CIN   64
#define CMOD  128          // d_model
#define HW    64           // output spatial side
#define L     4096         // HW*HW
#define M_TOT (BATCH*L)    // 16384 token rows
#define DIN   256          // d_inner
#define DST   16           // d_state
#define DTR   8            // dt_rank
#define NC    32           // scan chunks
#define LC    128          // chunk length (NC*LC == L)
#define NL    (BATCH*DIN*DST)   // 16384 scan lanes
#define LP    132          // padded l-stride for transposed smem

typedef unsigned long long ull;

// ---------------- scratch (device globals; no allocs allowed) ----------------
__device__ float g_y   [BATCH * CMOD * L];   // gelu(bn(conv)) in [b][c][l]
__device__ float g_xz  [M_TOT * 2 * DIN];    // in-proj output [m][512]
__device__ float g_bc  [M_TOT * 32];         // [m][32] : B(16) | C(16)
__device__ float g_del [M_TOT * DIN];        // delta[m][d]
__device__ float g_du  [M_TOT * DIN];        // delta*xin
__device__ float g_xd  [M_TOT * DIN];        // xin*Dp
__device__ float g_yg  [M_TOT * DIN];        // gated scan output [m][256]
__device__ float g_q   [NC * NL];            // [ch][lane] chunk local final state
__device__ float g_ap  [NC * NL];            // [ch][lane] chunk decay aggregate
__device__ float g_hin [NC * NL];            // [ch][lane] state entering chunk

// ---------------- helpers ----------------
__device__ __forceinline__ float silu_f(float v){ return v / (1.f + __expf(-v)); }
__device__ __forceinline__ float softplus_f(float v){ return (v > 20.f) ? v : log1pf(__expf(v)); }
__device__ __forceinline__ float gelu_f(float v){ return 0.5f * v * (1.f + erff(v * 0.70710678118654752f)); }

__device__ __forceinline__ ull pack2(float lo, float hi){
    ull r; asm("mov.b64 %0, {%1, %2};" : "=l"(r) : "f"(lo), "f"(hi)); return r;
}
__device__ __forceinline__ void ffma2(ull& d, ull a, ull b){
    asm("fma.rn.f32x2 %0, %1, %2, %0;" : "+l"(d) : "l"(a), "l"(b));
}
__device__ __forceinline__ float2 unpack2(ull v){
    float2 r; asm("mov.b64 {%0, %1}, %2;" : "=f"(r.x), "=f"(r.y) : "l"(v)); return r;
}

union f4u { float4 f; ull u[2]; };

// =====================================================================
// K1: conv3x3 stride2 pad1 (64->128ch) + bias + BN(eval) + exact GELU
// R13 structure (16x16 tile, 2-ci chunks, 256 thr, 4 blocks/SM)
// + float4 weight LDS (halves weight-load instruction count)
// =====================================================================
#define HALO (33*33)
#define HALO2 (2*HALO)

__global__ void __launch_bounds__(256, 4)
k_conv(const float* __restrict__ x, const float* __restrict__ w,
       const float* __restrict__ cb, const float* __restrict__ bng,
       const float* __restrict__ bnb, const float* __restrict__ bnm,
       const float* __restrict__ bnv)
{
    __shared__ float in_s[HALO2];            // 2 ci x 33x33 halo (8.7 KB)
    __shared__ __align__(16) float w_s[2 * 9 * 16];

    const int t  = threadIdx.x;              // 0..255
    const int tx = t & 15;                   // col 0..15
    const int ty = t >> 4;                   // row 0..15
    const int bx = blockIdx.x;
    const int oh0 = (bx >> 2) * 16, ow0 = (bx & 3) * 16;
    const int oc0 = blockIdx.y * 16;
    const int b   = blockIdx.z;
    const int ih0 = oh0 * 2 - 1, iw0 = ow0 * 2 - 1;

    ull acc2[8];
    #pragma unroll
    for (int o = 0; o < 8; o++) acc2[o] = 0ull;

    for (int cc = 0; cc < CIN; cc += 2) {
        __syncthreads();
        for (int idx = t; idx < HALO2; idx += 256) {
            int ci = idx / HALO, rem = idx - ci * HALO;
            int r = rem / 33, cl = rem - r * 33;
            int ih = ih0 + r, iw = iw0 + cl;
            float v = 0.f;
            if (ih >= 0 && ih < 128 && iw >= 0 && iw < 128)
                v = x[((b * CIN + cc + ci) * 128 + ih) * 128 + iw];
            in_s[idx] = v;
        }
        for (int idx = t; idx < 288; idx += 256) {
            int oc = idx & 15, rk = idx >> 4;    // rk = ci*9 + k, 0..17
            int ci = rk / 9, k = rk - ci * 9;
            w_s[idx] = w[(oc0 + oc) * (CIN * 9) + (cc + ci) * 9 + k];
        }
        __syncthreads();

        #pragma unroll
        for (int ci = 0; ci < 2; ci++)
            #pragma unroll
            for (int kh = 0; kh < 3; kh++) {
                const int r = 2 * ty + kh;
                #pragma unroll
                for (int kw = 0; kw < 3; kw++) {
                    const float4* wp4 = (const float4*)&w_s[(ci * 9 + kh * 3 + kw) * 16];
                    f4u w0, w1, w2, w3;
                    w0.f = wp4[0]; w1.f = wp4[1]; w2.f = wp4[2]; w3.f = wp4[3];
                    float iv = in_s[ci * HALO + r * 33 + 2 * tx + kw];
                    ull iv2 = pack2(iv, iv);
                    ffma2(acc2[0], iv2, w0.u[0]); ffma2(acc2[1], iv2, w0.u[1]);
                    ffma2(acc2[2], iv2, w1.u[0]); ffma2(acc2[3], iv2, w1.u[1]);
                    ffma2(acc2[4], iv2, w2.u[0]); ffma2(acc2[5], iv2, w2.u[1]);
                    ffma2(acc2[6], iv2, w3.u[0]); ffma2(acc2[7], iv2, w3.u[1]);
                }
            }
    }

    const int oh = oh0 + ty, ow = ow0 + tx;
    #pragma unroll
    for (int o = 0; o < 8; o++) {
        float2 pv = unpack2(acc2[o]);
        #pragma unroll
        for (int half = 0; half < 2; half++) {
            int c = oc0 + o * 2 + half;
            float inv = bng[c] * rsqrtf(bnv[c] + 1e-5f);
            float v = ((half ? pv.y : pv.x) + cb[c] - bnm[c]) * inv + bnb[c];
            g_y[(b * CMOD + c) * L + oh * HW + ow] = gelu_f(v);
        }
    }
}

// =====================================================================
// K2: in-proj GEMM  xz[m][e] = sum_k y[b][k][l] * in_w[e][k]
// BM=128, BE=128, BK=16 single-buffered ; float4 smem loads
// =====================================================================
__global__ void k_gemm_xz(const float* __restrict__ in_w)
{
    __shared__ __align__(16) float As[16][128];
    __shared__ __align__(16) float Bs[16][128];
    const int t  = threadIdx.x;
    const int tx = t & 15, ty = t >> 4;
    const int e0 = blockIdx.x * 128;
    const int m0 = blockIdx.y * 128;
    const int b  = m0 >> 12;
    const int l0 = m0 & 4095;

    const int arow4 = (t & 31) * 4;
    const int ak    = t >> 5;
    const int brow  = t >> 1;
    const int bkq   = (t & 1) * 4;

    ull acc2[8][4];
    #pragma unroll
    for (int i = 0; i < 8; i++)
        #pragma unroll
        for (int j = 0; j < 4; j++) acc2[i][j] = 0ull;

    for (int k0 = 0; k0 < CMOD; k0 += 16) {
        __syncthreads();
        {
            float4 a0 = *(const float4*)&g_y[(b * CMOD + k0 + ak) * L + l0 + arow4];
            float4 a1 = *(const float4*)&g_y[(b * CMOD + k0 + 8 + ak) * L + l0 + arow4];
            *(float4*)&As[ak][arow4] = a0;
            *(float4*)&As[ak + 8][arow4] = a1;
            float4 b0 = *(const float4*)&in_w[(e0 + brow) * CMOD + k0 + bkq];
            float4 b1 = *(const float4*)&in_w[(e0 + brow) * CMOD + k0 + bkq + 8];
            Bs[bkq + 0][brow] = b0.x; Bs[bkq + 1][brow] = b0.y;
            Bs[bkq + 2][brow] = b0.z; Bs[bkq + 3][brow] = b0.w;
            Bs[bkq + 8][brow] = b1.x; Bs[bkq + 9][brow] = b1.y;
            Bs[bkq +10][brow] = b1.z; Bs[bkq +11][brow] = b1.w;
        }
        __syncthreads();
        #pragma unroll
        for (int k = 0; k < 16; k++) {
            float a[8];
            *(float4*)&a[0] = *(float4*)&As[k][ty * 4];
            *(float4*)&a[4] = *(float4*)&As[k][ty * 4 + 64];
            f4u bl, bh;
            bl.f = *(const float4*)&Bs[k][tx * 4];
            bh.f = *(const float4*)&Bs[k][tx * 4 + 64];
            #pragma unroll
            for (int i = 0; i < 8; i++) {
                ull a2 = pack2(a[i], a[i]);
                ffma2(acc2[i][0], a2, bl.u[0]);
                ffma2(acc2[i][1], a2, bl.u[1]);
                ffma2(acc2[i][2], a2, bh.u[0]);
                ffma2(acc2[i][3], a2, bh.u[1]);
            }
        }
    }
    #pragma unroll
    for (int i = 0; i < 8; i++) {
        int m = m0 + ty * 4 + (i & 3) + (i >> 2) * 64;
        float2 p0 = unpack2(acc2[i][0]), p1 = unpack2(acc2[i][1]);
        float2 p2 = unpack2(acc2[i][2]), p3 = unpack2(acc2[i][3]);
        float4 v0 = make_float4(p0.x, p0.y, p1.x, p1.y);
        float4 v1 = make_float4(p2.x, p2.y, p3.x, p3.y);
        *(float4*)&g_xz[(size_t)m * 512 + e0 + tx * 4] = v0;
        *(float4*)&g_xz[(size_t)m * 512 + e0 + tx * 4 + 64] = v1;
    }
}

// =====================================================================
// K3: FUSED conv1d+SiLU + x-proj + delta/softplus + precompute
// =====================================================================
__global__ void k_cproj(const float* __restrict__ w, const float* __restrict__ bias,
                        const float* __restrict__ xpw, const float* __restrict__ dtw_g,
                        const float* __restrict__ dtb_g, const float* __restrict__ Dp_g)
{
    __shared__ float As[32 * 257];
    __shared__ float misc[2560];
    __shared__ float dt_sm[32][8];

    const int t  = threadIdx.x;
    const int m0 = blockIdx.x * 32;
    const int b  = m0 >> 12;
    const int l0 = m0 & 4095;

    {
        const int d = t;
        const float w0 = w[d * 4 + 0], w1 = w[d * 4 + 1], w2 = w[d * 4 + 2], w3 = w[d * 4 + 3];
        const float bs = bias[d];
        float xm3 = (l0 >= 3) ? g_xz[(size_t)(b * L + l0 - 3) * 512 + d] : 0.f;
        float xm2 = (l0 >= 2) ? g_xz[(size_t)(b * L + l0 - 2) * 512 + d] : 0.f;
        float xm1 = (l0 >= 1) ? g_xz[(size_t)(b * L + l0 - 1) * 512 + d] : 0.f;
        #pragma unroll 4
        for (int l = 0; l < 32; l++) {
            float xc = g_xz[(size_t)(b * L + l0 + l) * 512 + d];
            float v = fmaf(w0, xm3, fmaf(w1, xm2, fmaf(w2, xm1, fmaf(w3, xc, bs))));
            As[l * 257 + d] = silu_f(v);
            xm3 = xm2; xm2 = xm1; xm1 = xc;
        }
    }

    const int tx = t & 7;
    const int ty = t >> 3;
    float acc[5] = {0.f, 0.f, 0.f, 0.f, 0.f};

    for (int k0 = 0; k0 < 256; k0 += 32) {
        __syncthreads();
        for (int idx = t; idx < 320; idx += 256) {
            int e = idx >> 3, k4 = idx & 7;
            float4 v = *(const float4*)&xpw[e * 256 + k0 + k4 * 4];
            misc[(k4 * 4 + 0) * 41 + e] = v.x; misc[(k4 * 4 + 1) * 41 + e] = v.y;
            misc[(k4 * 4 + 2) * 41 + e] = v.z; misc[(k4 * 4 + 3) * 41 + e] = v.w;
        }
        __syncthreads();
        #pragma unroll
        for (int k = 0; k < 32; k++) {
            float a = As[ty * 257 + k0 + k];
            #pragma unroll
            for (int j = 0; j < 5; j++)
                acc[j] = fmaf(a, misc[k * 41 + tx * 5 + j], acc[j]);
        }
    }
    __syncthreads();

    #pragma unroll
    for (int j = 0; j < 5; j++) {
        int e = tx * 5 + j;
        if (e < 8) dt_sm[ty][e] = acc[j];
        else       g_bc[(size_t)(m0 + ty) * 32 + (e - 8)] = acc[j];
    }
    for (int idx = t; idx < 2048; idx += 256)
        misc[(idx & 7) * 256 + (idx >> 3)] = dtw_g[idx];
    misc[2048 + t] = dtb_g[t];
    misc[2304 + t] = Dp_g[t];
    __syncthreads();

    {
        const int d = t;
        float wv[8];
        #pragma unroll
        for (int r = 0; r < 8; r++) wv[r] = misc[r * 256 + d];
        const float dtbv = misc[2048 + d];
        const float Dpv  = misc[2304 + d];
        #pragma unroll 4
        for (int m = 0; m < 32; m++) {
            float s = dtbv;
            #pragma unroll
            for (int r = 0; r < 8; r++) s = fmaf(dt_sm[m][r], wv[r], s);
            float delta = softplus_f(s);
            float xv = As[m * 257 + d];
            size_t o = (size_t)(m0 + m) * 256 + d;
            g_del[o] = delta;
            g_du[o]  = delta * xv;
            g_xd[o]  = xv * Dpv;
        }
    }
}

// =====================================================================
// K5a: scan phase 1 — transposed l-major smem, float4 per 4 steps
// =====================================================================
__global__ void k_scan1(const float* __restrict__ A_log)
{
    __shared__ __align__(16) float del_t[8 * LP];
    __shared__ __align__(16) float du_t [8 * LP];
    __shared__ __align__(16) float B_t  [16 * LP];

    const int b  = blockIdx.z;
    const int ch = blockIdx.y;
    const int d0 = blockIdx.x * 8;
    const int t  = threadIdx.x;
    const int n  = t & 15, dl = t >> 4;
    const float A_dn = -__expf(A_log[(d0 + dl) * DST + n]);
    const int mb = b * L + ch * LC;

    #pragma unroll
    for (int j = 0; j < 2; j++) {
        int i4 = t + j * 128; int l = i4 >> 1, q = i4 & 1;
        float4 v = *(const float4*)&g_del[(size_t)(mb + l) * 256 + d0 + q * 4];
        del_t[(q * 4 + 0) * LP + l] = v.x; del_t[(q * 4 + 1) * LP + l] = v.y;
        del_t[(q * 4 + 2) * LP + l] = v.z; del_t[(q * 4 + 3) * LP + l] = v.w;
        float4 u = *(const float4*)&g_du[(size_t)(mb + l) * 256 + d0 + q * 4];
        du_t[(q * 4 + 0) * LP + l] = u.x; du_t[(q * 4 + 1) * LP + l] = u.y;
        du_t[(q * 4 + 2) * LP + l] = u.z; du_t[(q * 4 + 3) * LP + l] = u.w;
    }
    #pragma unroll
    for (int j = 0; j < 4; j++) {
        int i4 = t + j * 128; int l = i4 >> 2, q = i4 & 3;
        float4 v = *(const float4*)&g_bc[(size_t)(mb + l) * 32 + q * 4];
        B_t[(q * 4 + 0) * LP + l] = v.x; B_t[(q * 4 + 1) * LP + l] = v.y;
        B_t[(q * 4 + 2) * LP + l] = v.z; B_t[(q * 4 + 3) * LP + l] = v.w;
    }
    __syncthreads();

    float h = 0.f, sdel = 0.f;
    const float* dp = &del_t[dl * LP];
    const float* up = &du_t[dl * LP];
    const float* bp = &B_t[n * LP];
    #pragma unroll 4
    for (int l4 = 0; l4 < LC; l4 += 4) {
        float4 d4 = *(const float4*)&dp[l4];
        float4 u4 = *(const float4*)&up[l4];
        float4 b4 = *(const float4*)&bp[l4];
        h = fmaf(__expf(d4.x * A_dn), h, u4.x * b4.x);
        h = fmaf(__expf(d4.y * A_dn), h, u4.y * b4.y);
        h = fmaf(__expf(d4.z * A_dn), h, u4.z * b4.z);
        h = fmaf(__expf(d4.w * A_dn), h, u4.w * b4.w);
        sdel += (d4.x + d4.y) + (d4.z + d4.w);
    }
    const int lane = (b * DIN + d0) * DST + t;
    g_q [ch * NL + lane] = h;
    g_ap[ch * NL + lane] = __expf(A_dn * sdel);
}

// =====================================================================
// K5b: scan phase 2 — combine chunk aggregates
// =====================================================================
__global__ void k_scan2()
{
    const int lane = blockIdx.x * 128 + threadIdx.x;
    float h = 0.f;
    #pragma unroll
    for (int ch = 0; ch < NC; ch++) {
        g_hin[ch * NL + lane] = h;
        h = fmaf(g_ap[ch * NL + lane], h, g_q[ch * NL + lane]);
    }
}

// =====================================================================
// K5c: scan phase 3 — transposed staging + STS n-reduction + gate
// =====================================================================
__global__ void k_scan3(const float* __restrict__ A_log)
{
    __shared__ __align__(16) float del_t[8 * LP];
    __shared__ __align__(16) float du_t [8 * LP];
    __shared__ __align__(16) float B_t  [16 * LP];
    __shared__ __align__(16) float C_t  [16 * LP];
    __shared__ __align__(16) float ys_s [LC * 8];
    __shared__ float ysp[32 * 8 * 17];

    const int b  = blockIdx.z;
    const int ch = blockIdx.y;
    const int d0 = blockIdx.x * 8;
    const int t  = threadIdx.x;
    const int n  = t & 15, dl = t >> 4;
    const float A_dn = -__expf(A_log[(d0 + dl) * DST + n]);
    const int mb = b * L + ch * LC;

    #pragma unroll
    for (int j = 0; j < 2; j++) {
        int i4 = t + j * 128; int l = i4 >> 1, q = i4 & 1;
        float4 v = *(const float4*)&g_del[(size_t)(mb + l) * 256 + d0 + q * 4];
        del_t[(q * 4 + 0) * LP + l] = v.x; del_t[(q * 4 + 1) * LP + l] = v.y;
        del_t[(q * 4 + 2) * LP + l] = v.z; del_t[(q * 4 + 3) * LP + l] = v.w;
        float4 u = *(const float4*)&g_du[(size_t)(mb + l) * 256 + d0 + q * 4];
        du_t[(q * 4 + 0) * LP + l] = u.x; du_t[(q * 4 + 1) * LP + l] = u.y;
        du_t[(q * 4 + 2) * LP + l] = u.z; du_t[(q * 4 + 3) * LP + l] = u.w;
    }
    #pragma unroll
    for (int j = 0; j < 8; j++) {
        int i4 = t + j * 128; int l = i4 >> 3, q = i4 & 7;
        float4 v = *(const float4*)&g_bc[(size_t)(mb + l) * 32 + q * 4];
        float* dst = (q < 4) ? &B_t[(q * 4) * LP + l] : &C_t[((q - 4) * 4) * LP + l];
        dst[0 * LP] = v.x; dst[1 * LP] = v.y; dst[2 * LP] = v.z; dst[3 * LP] = v.w;
    }
    __syncthreads();

    const int lane = (b * DIN + d0) * DST + t;
    float h = g_hin[ch * NL + lane];
    const float* dp = &del_t[dl * LP];
    const float* up = &du_t[dl * LP];
    const float* bp = &B_t[n * LP];
    const float* cp = &C_t[n * LP];

    #pragma unroll
    for (int qq = 0; qq < 4; qq++) {
        #pragma unroll 4
        for (int li = 0; li < 32; li += 4) {
            int l = qq * 32 + li;
            float4 d4 = *(const float4*)&dp[l];
            float4 u4 = *(const float4*)&up[l];
            float4 b4 = *(const float4*)&bp[l];
            float4 c4 = *(const float4*)&cp[l];
            h = fmaf(__expf(d4.x * A_dn), h, u4.x * b4.x);
            ysp[((li + 0) * 8 + dl) * 17 + n] = h * c4.x;
            h = fmaf(__expf(d4.y * A_dn), h, u4.y * b4.y);
            ysp[((li + 1) * 8 + dl) * 17 + n] = h * c4.y;
            h = fmaf(__expf(d4.z * A_dn), h, u4.z * b4.z);
            ysp[((li + 2) * 8 + dl) * 17 + n] = h * c4.z;
            h = fmaf(__expf(d4.w * A_dn), h, u4.w * b4.w);
            ysp[((li + 3) * 8 + dl) * 17 + n] = h * c4.w;
        }
        __syncthreads();
        #pragma unroll
        for (int rep = 0; rep < 2; rep++) {
            int idx = t + rep * 128;
            int ll = idx >> 3, dd = idx & 7;
            float s = 0.f;
            #pragma unroll
            for (int nn = 0; nn < 16; nn++)
                s += ysp[(ll * 8 + dd) * 17 + nn];
            ys_s[(qq * 32 + ll) * 8 + dd] = s;
        }
        __syncthreads();
    }

    #pragma unroll
    for (int j = 0; j < 2; j++) {
        int i4 = t + j * 128; int l = i4 >> 1, q = i4 & 1;
        float4 z4 = *(const float4*)&g_xz[(size_t)(mb + l) * 512 + 256 + d0 + q * 4];
        float4 xd = *(const float4*)&g_xd[(size_t)(mb + l) * 256 + d0 + q * 4];
        float4 ys = *(const float4*)&ys_s[l * 8 + q * 4];
        float4 o;
        o.x = (ys.x + xd.x) * silu_f(z4.x);
        o.y = (ys.y + xd.y) * silu_f(z4.y);
        o.z = (ys.z + xd.z) * silu_f(z4.z);
        o.w = (ys.w + xd.w) * silu_f(z4.w);
        *(float4*)&g_yg[(size_t)(mb + l) * 256 + d0 + q * 4] = o;
    }
}

// =====================================================================
// K6: out-proj GEMM + residual, BK=16 single-buffered; float4 smem loads
// =====================================================================
__global__ void k_gemm_out(const float* __restrict__ ow, float* __restrict__ out)
{
    __shared__ __align__(16) float As[16][128];
    __shared__ __align__(16) float Bs[16][128];
    const int t  = threadIdx.x;
    const int tx = t & 15, ty = t >> 4;
    const int m0 = blockIdx.x * 128;
    const int b  = m0 >> 12;
    const int l0 = m0 & 4095;

    const int row = t >> 1;
    const int kq  = (t & 1) * 4;

    ull acc2[8][4];
    #pragma unroll
    for (int i = 0; i < 8; i++)
        #pragma unroll
        for (int j = 0; j < 4; j++) acc2[i][j] = 0ull;

    for (int k0 = 0; k0 < DIN; k0 += 16) {
        __syncthreads();
        {
            float4 a0 = *(const float4*)&g_yg[(size_t)(m0 + row) * DIN + k0 + kq];
            float4 a1 = *(const float4*)&g_yg[(size_t)(m0 + row) * DIN + k0 + kq + 8];
            As[kq + 0][row] = a0.x; As[kq + 1][row] = a0.y;
            As[kq + 2][row] = a0.z; As[kq + 3][row] = a0.w;
            As[kq + 8][row] = a1.x; As[kq + 9][row] = a1.y;
            As[kq +10][row] = a1.z; As[kq +11][row] = a1.w;
            float4 b0 = *(const float4*)&ow[row * DIN + k0 + kq];
            float4 b1 = *(const float4*)&ow[row * DIN + k0 + kq + 8];
            Bs[kq + 0][row] = b0.x; Bs[kq + 1][row] = b0.y;
            Bs[kq + 2][row] = b0.z; Bs[kq + 3][row] = b0.w;
            Bs[kq + 8][row] = b1.x; Bs[kq + 9][row] = b1.y;
            Bs[kq +10][row] = b1.z; Bs[kq +11][row] = b1.w;
        }
        __syncthreads();
        #pragma unroll
        for (int k = 0; k < 16; k++) {
            f4u al, ah;
            al.f = *(const float4*)&As[k][tx * 4];
            ah.f = *(const float4*)&As[k][tx * 4 + 64];
            float bc[8];
            *(float4*)&bc[0] = *(float4*)&Bs[k][ty * 4];
            *(float4*)&bc[4] = *(float4*)&Bs[k][ty * 4 + 64];
            #pragma unroll
            for (int ci = 0; ci < 8; ci++) {
                ull c2 = pack2(bc[ci], bc[ci]);
                ffma2(acc2[ci][0], c2, al.u[0]);
                ffma2(acc2[ci][1], c2, al.u[1]);
                ffma2(acc2[ci][2], c2, ah.u[0]);
                ffma2(acc2[ci][3], c2, ah.u[1]);
            }
        }
    }
    #pragma unroll
    for (int ci = 0; ci < 8; ci++) {
        int c = ty * 4 + (ci & 3) + (ci >> 2) * 64;
        size_t base = (size_t)(b * CMOD + c) * L + l0;
        float2 p0 = unpack2(acc2[ci][0]), p1 = unpack2(acc2[ci][1]);
        float2 p2 = unpack2(acc2[ci][2]), p3 = unpack2(acc2[ci][3]);
        float4 r0 = *(const float4*)&g_y[base + tx * 4];
        r0.x += p0.x; r0.y += p0.y; r0.z += p1.x; r0.w += p1.y;
        *(float4*)&out[base + tx * 4] = r0;
        float4 r1 = *(const float4*)&g_y[base + tx * 4 + 64];
        r1.x += p2.x; r1.y += p2.y; r1.z += p3.x; r1.w += p3.y;
        *(float4*)&out[base + tx * 4 + 64] = r1;
    }
}

// =====================================================================
extern "C" void kernel_launch(void* const* d_in, const int* in_sizes, int n_in,
                              void* d_out, int out_size)
{
    const float* x        = (const float*)d_in[0];
    const float* conv_w   = (const float*)d_in[1];
    const float* conv_b   = (const float*)d_in[2];
    const float* bn_g     = (const float*)d_in[3];
    const float* bn_b     = (const float*)d_in[4];
    const float* bn_mean  = (const float*)d_in[5];
    const float* bn_var   = (const float*)d_in[6];
    const float* in_w     = (const float*)d_in[7];
    const float* conv1d_w = (const float*)d_in[8];
    const float* conv1d_b = (const float*)d_in[9];
    const float* xproj_w  = (const float*)d_in[10];
    const float* dtproj_w = (const float*)d_in[11];
    const float* dtproj_b = (const float*)d_in[12];
    const float* A_log    = (const float*)d_in[13];
    const float* Dp       = (const float*)d_in[14];
    const float* out_w    = (const float*)d_in[15];
    float* out = (float*)d_out;

    k_conv    <<<dim3(16, 8, 4), 256>>>(x, conv_w, conv_b, bn_g, bn_b, bn_mean, bn_var);
    k_gemm_xz <<<dim3(4, 128), 256>>>(in_w);
    k_cproj   <<<512, 256>>>(conv1d_w, conv1d_b, xproj_w, dtproj_w, dtproj_b, Dp);
    k_scan1   <<<dim3(32, NC, 4), 128>>>(A_log);
    k_scan2   <<<128, 128>>>();
    k_scan3   <<<dim3(32, NC, 4), 128>>>(A_log);
    k_gemm_out<<<128, 256>>>(out_w, out);
}

// round 17
// speedup vs baseline: 1.0725x; 1.0097x over previous
#include <cuda_runtime.h>
#include <math.h>

// ---------------- problem constants ----------------
#define BATCH 4
#define CIN   64
#define CMOD  128          // d_model
#define HW    64           // output spatial side
#define L     4096         // HW*HW
#define M_TOT (BATCH*L)    // 16384 token rows
#define DIN   256          // d_inner
#define DST   16           // d_state
#define DTR   8            // dt_rank
#define NC    32           // scan chunks
#define LC    128          // chunk length (NC*LC == L)
#define NL    (BATCH*DIN*DST)   // 16384 scan lanes
#define LP    132          // padded l-stride for transposed smem

typedef unsigned long long ull;

// ---------------- scratch (device globals; no allocs allowed) ----------------
__device__ float g_y   [BATCH * CMOD * L];   // gelu(bn(conv)) in [b][c][l]
__device__ float g_xz  [M_TOT * 2 * DIN];    // in-proj output [m][512]
__device__ float g_bc  [M_TOT * 32];         // [m][32] : B(16) | C(16)
__device__ float g_del [M_TOT * DIN];        // delta[m][d]
__device__ float g_du  [M_TOT * DIN];        // delta*xin
__device__ float g_xd  [M_TOT * DIN];        // xin*Dp
__device__ float g_yg  [M_TOT * DIN];        // gated scan output [m][256]
__device__ float g_q   [NC * NL];            // [ch][lane] chunk local final state
__device__ float g_ap  [NC * NL];            // [ch][lane] chunk decay aggregate
__device__ float g_hin [NC * NL];            // [ch][lane] state entering chunk

// ---------------- helpers ----------------
__device__ __forceinline__ float silu_f(float v){ return v / (1.f + __expf(-v)); }
__device__ __forceinline__ float softplus_f(float v){ return (v > 20.f) ? v : log1pf(__expf(v)); }
__device__ __forceinline__ float gelu_f(float v){ return 0.5f * v * (1.f + erff(v * 0.70710678118654752f)); }

__device__ __forceinline__ ull pack2(float lo, float hi){
    ull r; asm("mov.b64 %0, {%1, %2};" : "=l"(r) : "f"(lo), "f"(hi)); return r;
}
__device__ __forceinline__ void ffma2(ull& d, ull a, ull b){
    asm("fma.rn.f32x2 %0, %1, %2, %0;" : "+l"(d) : "l"(a), "l"(b));
}
__device__ __forceinline__ float2 unpack2(ull v){
    float2 r; asm("mov.b64 {%0, %1}, %2;" : "=f"(r.x), "=f"(r.y) : "l"(v)); return r;
}

union f4u { float4 f; ull u[2]; };

// =====================================================================
// K1: conv3x3 stride2 pad1 (64->128ch) + bias + BN(eval) + exact GELU
// v6: 32 oc per block (16 ull accs), 16x16 tile, 256 threads
// grid (16 spatial, 4 oc, 4 b) = 256 blocks ; input re-read 4x (was 8x)
// =====================================================================
#define HALO (33*33)
#define HALO2 (2*HALO)

__global__ void __launch_bounds__(256, 3)
k_conv(const float* __restrict__ x, const float* __restrict__ w,
       const float* __restrict__ cb, const float* __restrict__ bng,
       const float* __restrict__ bnb, const float* __restrict__ bnm,
       const float* __restrict__ bnv)
{
    __shared__ float in_s[HALO2];                     // 8.7 KB
    __shared__ __align__(16) float w_s[2 * 9 * 32];   // 2.3 KB

    const int t  = threadIdx.x;              // 0..255
    const int tx = t & 15;                   // col 0..15
    const int ty = t >> 4;                   // row 0..15
    const int bx = blockIdx.x;
    const int oh0 = (bx >> 2) * 16, ow0 = (bx & 3) * 16;
    const int oc0 = blockIdx.y * 32;
    const int b   = blockIdx.z;
    const int ih0 = oh0 * 2 - 1, iw0 = ow0 * 2 - 1;

    ull acc2[16];
    #pragma unroll
    for (int o = 0; o < 16; o++) acc2[o] = 0ull;

    for (int cc = 0; cc < CIN; cc += 2) {
        __syncthreads();
        for (int idx = t; idx < HALO2; idx += 256) {
            int ci = idx / HALO, rem = idx - ci * HALO;
            int r = rem / 33, cl = rem - r * 33;
            int ih = ih0 + r, iw = iw0 + cl;
            float v = 0.f;
            if (ih >= 0 && ih < 128 && iw >= 0 && iw < 128)
                v = x[((b * CIN + cc + ci) * 128 + ih) * 128 + iw];
            in_s[idx] = v;
        }
        for (int idx = t; idx < 576; idx += 256) {
            int oc = idx & 31, rk = idx >> 5;    // rk = ci*9 + k, 0..17
            int ci = rk / 9, k = rk - ci * 9;
            w_s[idx] = w[(oc0 + oc) * (CIN * 9) + (cc + ci) * 9 + k];
        }
        __syncthreads();

        #pragma unroll
        for (int ci = 0; ci < 2; ci++)
            #pragma unroll
            for (int kh = 0; kh < 3; kh++) {
                const int r = 2 * ty + kh;
                #pragma unroll
                for (int kw = 0; kw < 3; kw++) {
                    const float4* wp4 = (const float4*)&w_s[(ci * 9 + kh * 3 + kw) * 32];
                    float iv = in_s[ci * HALO + r * 33 + 2 * tx + kw];
                    ull iv2 = pack2(iv, iv);
                    #pragma unroll
                    for (int q = 0; q < 8; q++) {
                        f4u wq; wq.f = wp4[q];
                        ffma2(acc2[q * 2 + 0], iv2, wq.u[0]);
                        ffma2(acc2[q * 2 + 1], iv2, wq.u[1]);
                    }
                }
            }
    }

    const int oh = oh0 + ty, ow = ow0 + tx;
    #pragma unroll
    for (int o = 0; o < 16; o++) {
        float2 pv = unpack2(acc2[o]);
        #pragma unroll
        for (int half = 0; half < 2; half++) {
            int c = oc0 + o * 2 + half;
            float inv = bng[c] * rsqrtf(bnv[c] + 1e-5f);
            float v = ((half ? pv.y : pv.x) + cb[c] - bnm[c]) * inv + bnb[c];
            g_y[(b * CMOD + c) * L + oh * HW + ow] = gelu_f(v);
        }
    }
}

// =====================================================================
// K2: in-proj GEMM  xz[m][e] = sum_k y[b][k][l] * in_w[e][k]
// BM=128, BE=128, BK=16 single-buffered ; float4 smem loads
// =====================================================================
__global__ void k_gemm_xz(const float* __restrict__ in_w)
{
    __shared__ __align__(16) float As[16][128];
    __shared__ __align__(16) float Bs[16][128];
    const int t  = threadIdx.x;
    const int tx = t & 15, ty = t >> 4;
    const int e0 = blockIdx.x * 128;
    const int m0 = blockIdx.y * 128;
    const int b  = m0 >> 12;
    const int l0 = m0 & 4095;

    const int arow4 = (t & 31) * 4;
    const int ak    = t >> 5;
    const int brow  = t >> 1;
    const int bkq   = (t & 1) * 4;

    ull acc2[8][4];
    #pragma unroll
    for (int i = 0; i < 8; i++)
        #pragma unroll
        for (int j = 0; j < 4; j++) acc2[i][j] = 0ull;

    for (int k0 = 0; k0 < CMOD; k0 += 16) {
        __syncthreads();
        {
            float4 a0 = *(const float4*)&g_y[(b * CMOD + k0 + ak) * L + l0 + arow4];
            float4 a1 = *(const float4*)&g_y[(b * CMOD + k0 + 8 + ak) * L + l0 + arow4];
            *(float4*)&As[ak][arow4] = a0;
            *(float4*)&As[ak + 8][arow4] = a1;
            float4 b0 = *(const float4*)&in_w[(e0 + brow) * CMOD + k0 + bkq];
            float4 b1 = *(const float4*)&in_w[(e0 + brow) * CMOD + k0 + bkq + 8];
            Bs[bkq + 0][brow] = b0.x; Bs[bkq + 1][brow] = b0.y;
            Bs[bkq + 2][brow] = b0.z; Bs[bkq + 3][brow] = b0.w;
            Bs[bkq + 8][brow] = b1.x; Bs[bkq + 9][brow] = b1.y;
            Bs[bkq +10][brow] = b1.z; Bs[bkq +11][brow] = b1.w;
        }
        __syncthreads();
        #pragma unroll
        for (int k = 0; k < 16; k++) {
            float a[8];
            *(float4*)&a[0] = *(float4*)&As[k][ty * 4];
            *(float4*)&a[4] = *(float4*)&As[k][ty * 4 + 64];
            f4u bl, bh;
            bl.f = *(const float4*)&Bs[k][tx * 4];
            bh.f = *(const float4*)&Bs[k][tx * 4 + 64];
            #pragma unroll
            for (int i = 0; i < 8; i++) {
                ull a2 = pack2(a[i], a[i]);
                ffma2(acc2[i][0], a2, bl.u[0]);
                ffma2(acc2[i][1], a2, bl.u[1]);
                ffma2(acc2[i][2], a2, bh.u[0]);
                ffma2(acc2[i][3], a2, bh.u[1]);
            }
        }
    }
    #pragma unroll
    for (int i = 0; i < 8; i++) {
        int m = m0 + ty * 4 + (i & 3) + (i >> 2) * 64;
        float2 p0 = unpack2(acc2[i][0]), p1 = unpack2(acc2[i][1]);
        float2 p2 = unpack2(acc2[i][2]), p3 = unpack2(acc2[i][3]);
        float4 v0 = make_float4(p0.x, p0.y, p1.x, p1.y);
        float4 v1 = make_float4(p2.x, p2.y, p3.x, p3.y);
        *(float4*)&g_xz[(size_t)m * 512 + e0 + tx * 4] = v0;
        *(float4*)&g_xz[(size_t)m * 512 + e0 + tx * 4 + 64] = v1;
    }
}

// =====================================================================
// K3: FUSED conv1d+SiLU + x-proj + delta/softplus + precompute
// =====================================================================
__global__ void k_cproj(const float* __restrict__ w, const float* __restrict__ bias,
                        const float* __restrict__ xpw, const float* __restrict__ dtw_g,
                        const float* __restrict__ dtb_g, const float* __restrict__ Dp_g)
{
    __shared__ float As[32 * 257];
    __shared__ float misc[2560];
    __shared__ float dt_sm[32][8];

    const int t  = threadIdx.x;
    const int m0 = blockIdx.x * 32;
    const int b  = m0 >> 12;
    const int l0 = m0 & 4095;

    {
        const int d = t;
        const float w0 = w[d * 4 + 0], w1 = w[d * 4 + 1], w2 = w[d * 4 + 2], w3 = w[d * 4 + 3];
        const float bs = bias[d];
        float xm3 = (l0 >= 3) ? g_xz[(size_t)(b * L + l0 - 3) * 512 + d] : 0.f;
        float xm2 = (l0 >= 2) ? g_xz[(size_t)(b * L + l0 - 2) * 512 + d] : 0.f;
        float xm1 = (l0 >= 1) ? g_xz[(size_t)(b * L + l0 - 1) * 512 + d] : 0.f;
        #pragma unroll 4
        for (int l = 0; l < 32; l++) {
            float xc = g_xz[(size_t)(b * L + l0 + l) * 512 + d];
            float v = fmaf(w0, xm3, fmaf(w1, xm2, fmaf(w2, xm1, fmaf(w3, xc, bs))));
            As[l * 257 + d] = silu_f(v);
            xm3 = xm2; xm2 = xm1; xm1 = xc;
        }
    }

    const int tx = t & 7;
    const int ty = t >> 3;
    float acc[5] = {0.f, 0.f, 0.f, 0.f, 0.f};

    for (int k0 = 0; k0 < 256; k0 += 32) {
        __syncthreads();
        for (int idx = t; idx < 320; idx += 256) {
            int e = idx >> 3, k4 = idx & 7;
            float4 v = *(const float4*)&xpw[e * 256 + k0 + k4 * 4];
            misc[(k4 * 4 + 0) * 41 + e] = v.x; misc[(k4 * 4 + 1) * 41 + e] = v.y;
            misc[(k4 * 4 + 2) * 41 + e] = v.z; misc[(k4 * 4 + 3) * 41 + e] = v.w;
        }
        __syncthreads();
        #pragma unroll
        for (int k = 0; k < 32; k++) {
            float a = As[ty * 257 + k0 + k];
            #pragma unroll
            for (int j = 0; j < 5; j++)
                acc[j] = fmaf(a, misc[k * 41 + tx * 5 + j], acc[j]);
        }
    }
    __syncthreads();

    #pragma unroll
    for (int j = 0; j < 5; j++) {
        int e = tx * 5 + j;
        if (e < 8) dt_sm[ty][e] = acc[j];
        else       g_bc[(size_t)(m0 + ty) * 32 + (e - 8)] = acc[j];
    }
    for (int idx = t; idx < 2048; idx += 256)
        misc[(idx & 7) * 256 + (idx >> 3)] = dtw_g[idx];
    misc[2048 + t] = dtb_g[t];
    misc[2304 + t] = Dp_g[t];
    __syncthreads();

    {
        const int d = t;
        float wv[8];
        #pragma unroll
        for (int r = 0; r < 8; r++) wv[r] = misc[r * 256 + d];
        const float dtbv = misc[2048 + d];
        const float Dpv  = misc[2304 + d];
        #pragma unroll 4
        for (int m = 0; m < 32; m++) {
            float s = dtbv;
            #pragma unroll
            for (int r = 0; r < 8; r++) s = fmaf(dt_sm[m][r], wv[r], s);
            float delta = softplus_f(s);
            float xv = As[m * 257 + d];
            size_t o = (size_t)(m0 + m) * 256 + d;
            g_del[o] = delta;
            g_du[o]  = delta * xv;
            g_xd[o]  = xv * Dpv;
        }
    }
}

// =====================================================================
// K5a: scan phase 1 — transposed l-major smem, float4 per 4 steps
// =====================================================================
__global__ void k_scan1(const float* __restrict__ A_log)
{
    __shared__ __align__(16) float del_t[8 * LP];
    __shared__ __align__(16) float du_t [8 * LP];
    __shared__ __align__(16) float B_t  [16 * LP];

    const int b  = blockIdx.z;
    const int ch = blockIdx.y;
    const int d0 = blockIdx.x * 8;
    const int t  = threadIdx.x;
    const int n  = t & 15, dl = t >> 4;
    const float A_dn = -__expf(A_log[(d0 + dl) * DST + n]);
    const int mb = b * L + ch * LC;

    #pragma unroll
    for (int j = 0; j < 2; j++) {
        int i4 = t + j * 128; int l = i4 >> 1, q = i4 & 1;
        float4 v = *(const float4*)&g_del[(size_t)(mb + l) * 256 + d0 + q * 4];
        del_t[(q * 4 + 0) * LP + l] = v.x; del_t[(q * 4 + 1) * LP + l] = v.y;
        del_t[(q * 4 + 2) * LP + l] = v.z; del_t[(q * 4 + 3) * LP + l] = v.w;
        float4 u = *(const float4*)&g_du[(size_t)(mb + l) * 256 + d0 + q * 4];
        du_t[(q * 4 + 0) * LP + l] = u.x; du_t[(q * 4 + 1) * LP + l] = u.y;
        du_t[(q * 4 + 2) * LP + l] = u.z; du_t[(q * 4 + 3) * LP + l] = u.w;
    }
    #pragma unroll
    for (int j = 0; j < 4; j++) {
        int i4 = t + j * 128; int l = i4 >> 2, q = i4 & 3;
        float4 v = *(const float4*)&g_bc[(size_t)(mb + l) * 32 + q * 4];
        B_t[(q * 4 + 0) * LP + l] = v.x; B_t[(q * 4 + 1) * LP + l] = v.y;
        B_t[(q * 4 + 2) * LP + l] = v.z; B_t[(q * 4 + 3) * LP + l] = v.w;
    }
    __syncthreads();

    float h = 0.f, sdel = 0.f;
    const float* dp = &del_t[dl * LP];
    const float* up = &du_t[dl * LP];
    const float* bp = &B_t[n * LP];
    #pragma unroll 4
    for (int l4 = 0; l4 < LC; l4 += 4) {
        float4 d4 = *(const float4*)&dp[l4];
        float4 u4 = *(const float4*)&up[l4];
        float4 b4 = *(const float4*)&bp[l4];
        h = fmaf(__expf(d4.x * A_dn), h, u4.x * b4.x);
        h = fmaf(__expf(d4.y * A_dn), h, u4.y * b4.y);
        h = fmaf(__expf(d4.z * A_dn), h, u4.z * b4.z);
        h = fmaf(__expf(d4.w * A_dn), h, u4.w * b4.w);
        sdel += (d4.x + d4.y) + (d4.z + d4.w);
    }
    const int lane = (b * DIN + d0) * DST + t;
    g_q [ch * NL + lane] = h;
    g_ap[ch * NL + lane] = __expf(A_dn * sdel);
}

// =====================================================================
// K5b: scan phase 2 — combine chunk aggregates
// =====================================================================
__global__ void k_scan2()
{
    const int lane = blockIdx.x * 128 + threadIdx.x;
    float h = 0.f;
    #pragma unroll
    for (int ch = 0; ch < NC; ch++) {
        g_hin[ch * NL + lane] = h;
        h = fmaf(g_ap[ch * NL + lane], h, g_q[ch * NL + lane]);
    }
}

// =====================================================================
// K5c: scan phase 3 — transposed staging + STS n-reduction + gate
// =====================================================================
__global__ void k_scan3(const float* __restrict__ A_log)
{
    __shared__ __align__(16) float del_t[8 * LP];
    __shared__ __align__(16) float du_t [8 * LP];
    __shared__ __align__(16) float B_t  [16 * LP];
    __shared__ __align__(16) float C_t  [16 * LP];
    __shared__ __align__(16) float ys_s [LC * 8];
    __shared__ float ysp[32 * 8 * 17];

    const int b  = blockIdx.z;
    const int ch = blockIdx.y;
    const int d0 = blockIdx.x * 8;
    const int t  = threadIdx.x;
    const int n  = t & 15, dl = t >> 4;
    const float A_dn = -__expf(A_log[(d0 + dl) * DST + n]);
    const int mb = b * L + ch * LC;

    #pragma unroll
    for (int j = 0; j < 2; j++) {
        int i4 = t + j * 128; int l = i4 >> 1, q = i4 & 1;
        float4 v = *(const float4*)&g_del[(size_t)(mb + l) * 256 + d0 + q * 4];
        del_t[(q * 4 + 0) * LP + l] = v.x; del_t[(q * 4 + 1) * LP + l] = v.y;
        del_t[(q * 4 + 2) * LP + l] = v.z; del_t[(q * 4 + 3) * LP + l] = v.w;
        float4 u = *(const float4*)&g_du[(size_t)(mb + l) * 256 + d0 + q * 4];
        du_t[(q * 4 + 0) * LP + l] = u.x; du_t[(q * 4 + 1) * LP + l] = u.y;
        du_t[(q * 4 + 2) * LP + l] = u.z; du_t[(q * 4 + 3) * LP + l] = u.w;
    }
    #pragma unroll
    for (int j = 0; j < 8; j++) {
        int i4 = t + j * 128; int l = i4 >> 3, q = i4 & 7;
        float4 v = *(const float4*)&g_bc[(size_t)(mb + l) * 32 + q * 4];
        float* dst = (q < 4) ? &B_t[(q * 4) * LP + l] : &C_t[((q - 4) * 4) * LP + l];
        dst[0 * LP] = v.x; dst[1 * LP] = v.y; dst[2 * LP] = v.z; dst[3 * LP] = v.w;
    }
    __syncthreads();

    const int lane = (b * DIN + d0) * DST + t;
    float h = g_hin[ch * NL + lane];
    const float* dp = &del_t[dl * LP];
    const float* up = &du_t[dl * LP];
    const float* bp = &B_t[n * LP];
    const float* cp = &C_t[n * LP];

    #pragma unroll
    for (int qq = 0; qq < 4; qq++) {
        #pragma unroll 4
        for (int li = 0; li < 32; li += 4) {
            int l = qq * 32 + li;
            float4 d4 = *(const float4*)&dp[l];
            float4 u4 = *(const float4*)&up[l];
            float4 b4 = *(const float4*)&bp[l];
            float4 c4 = *(const float4*)&cp[l];
            h = fmaf(__expf(d4.x * A_dn), h, u4.x * b4.x);
            ysp[((li + 0) * 8 + dl) * 17 + n] = h * c4.x;
            h = fmaf(__expf(d4.y * A_dn), h, u4.y * b4.y);
            ysp[((li + 1) * 8 + dl) * 17 + n] = h * c4.y;
            h = fmaf(__expf(d4.z * A_dn), h, u4.z * b4.z);
            ysp[((li + 2) * 8 + dl) * 17 + n] = h * c4.z;
            h = fmaf(__expf(d4.w * A_dn), h, u4.w * b4.w);
            ysp[((li + 3) * 8 + dl) * 17 + n] = h * c4.w;
        }
        __syncthreads();
        #pragma unroll
        for (int rep = 0; rep < 2; rep++) {
            int idx = t + rep * 128;
            int ll = idx >> 3, dd = idx & 7;
            float s = 0.f;
            #pragma unroll
            for (int nn = 0; nn < 16; nn++)
                s += ysp[(ll * 8 + dd) * 17 + nn];
            ys_s[(qq * 32 + ll) * 8 + dd] = s;
        }
        __syncthreads();
    }

    #pragma unroll
    for (int j = 0; j < 2; j++) {
        int i4 = t + j * 128; int l = i4 >> 1, q = i4 & 1;
        float4 z4 = *(const float4*)&g_xz[(size_t)(mb + l) * 512 + 256 + d0 + q * 4];
        float4 xd = *(const float4*)&g_xd[(size_t)(mb + l) * 256 + d0 + q * 4];
        float4 ys = *(const float4*)&ys_s[l * 8 + q * 4];
        float4 o;
        o.x = (ys.x + xd.x) * silu_f(z4.x);
        o.y = (ys.y + xd.y) * silu_f(z4.y);
        o.z = (ys.z + xd.z) * silu_f(z4.z);
        o.w = (ys.w + xd.w) * silu_f(z4.w);
        *(float4*)&g_yg[(size_t)(mb + l) * 256 + d0 + q * 4] = o;
    }
}

// =====================================================================
// K6: out-proj GEMM + residual, BK=16 single-buffered; float4 smem loads
// =====================================================================
__global__ void k_gemm_out(const float* __restrict__ ow, float* __restrict__ out)
{
    __shared__ __align__(16) float As[16][128];
    __shared__ __align__(16) float Bs[16][128];
    const int t  = threadIdx.x;
    const int tx = t & 15, ty = t >> 4;
    const int m0 = blockIdx.x * 128;
    const int b  = m0 >> 12;
    const int l0 = m0 & 4095;

    const int row = t >> 1;
    const int kq  = (t & 1) * 4;

    ull acc2[8][4];
    #pragma unroll
    for (int i = 0; i < 8; i++)
        #pragma unroll
        for (int j = 0; j < 4; j++) acc2[i][j] = 0ull;

    for (int k0 = 0; k0 < DIN; k0 += 16) {
        __syncthreads();
        {
            float4 a0 = *(const float4*)&g_yg[(size_t)(m0 + row) * DIN + k0 + kq];
            float4 a1 = *(const float4*)&g_yg[(size_t)(m0 + row) * DIN + k0 + kq + 8];
            As[kq + 0][row] = a0.x; As[kq + 1][row] = a0.y;
            As[kq + 2][row] = a0.z; As[kq + 3][row] = a0.w;
            As[kq + 8][row] = a1.x; As[kq + 9][row] = a1.y;
            As[kq +10][row] = a1.z; As[kq +11][row] = a1.w;
            float4 b0 = *(const float4*)&ow[row * DIN + k0 + kq];
            float4 b1 = *(const float4*)&ow[row * DIN + k0 + kq + 8];
            Bs[kq + 0][row] = b0.x; Bs[kq + 1][row] = b0.y;
            Bs[kq + 2][row] = b0.z; Bs[kq + 3][row] = b0.w;
            Bs[kq + 8][row] = b1.x; Bs[kq + 9][row] = b1.y;
            Bs[kq +10][row] = b1.z; Bs[kq +11][row] = b1.w;
        }
        __syncthreads();
        #pragma unroll
        for (int k = 0; k < 16; k++) {
            f4u al, ah;
            al.f = *(const float4*)&As[k][tx * 4];
            ah.f = *(const float4*)&As[k][tx * 4 + 64];
            float bc[8];
            *(float4*)&bc[0] = *(float4*)&Bs[k][ty * 4];
            *(float4*)&bc[4] = *(float4*)&Bs[k][ty * 4 + 64];
            #pragma unroll
            for (int ci = 0; ci < 8; ci++) {
                ull c2 = pack2(bc[ci], bc[ci]);
                ffma2(acc2[ci][0], c2, al.u[0]);
                ffma2(acc2[ci][1], c2, al.u[1]);
                ffma2(acc2[ci][2], c2, ah.u[0]);
                ffma2(acc2[ci][3], c2, ah.u[1]);
            }
        }
    }
    #pragma unroll
    for (int ci = 0; ci < 8; ci++) {
        int c = ty * 4 + (ci & 3) + (ci >> 2) * 64;
        size_t base = (size_t)(b * CMOD + c) * L + l0;
        float2 p0 = unpack2(acc2[ci][0]), p1 = unpack2(acc2[ci][1]);
        float2 p2 = unpack2(acc2[ci][2]), p3 = unpack2(acc2[ci][3]);
        float4 r0 = *(const float4*)&g_y[base + tx * 4];
        r0.x += p0.x; r0.y += p0.y; r0.z += p1.x; r0.w += p1.y;
        *(float4*)&out[base + tx * 4] = r0;
        float4 r1 = *(const float4*)&g_y[base + tx * 4 + 64];
        r1.x += p2.x; r1.y += p2.y; r1.z += p3.x; r1.w += p3.y;
        *(float4*)&out[base + tx * 4 + 64] = r1;
    }
}

// =====================================================================
extern "C" void kernel_launch(void* const* d_in, const int* in_sizes, int n_in,
                              void* d_out, int out_size)
{
    const float* x        = (const float*)d_in[0];
    const float* conv_w   = (const float*)d_in[1];
    const float* conv_b   = (const float*)d_in[2];
    const float* bn_g     = (const float*)d_in[3];
    const float* bn_b     = (const float*)d_in[4];
    const float* bn_mean  = (const float*)d_in[5];
    const float* bn_var   = (const float*)d_in[6];
    const float* in_w     = (const float*)d_in[7];
    const float* conv1d_w = (const float*)d_in[8];
    const float* conv1d_b = (const float*)d_in[9];
    const float* xproj_w  = (const float*)d_in[10];
    const float* dtproj_w = (const float*)d_in[11];
    const float* dtproj_b = (const float*)d_in[12];
    const float* A_log    = (const float*)d_in[13];
    const float* Dp       = (const float*)d_in[14];
    const float* out_w    = (const float*)d_in[15];
    float* out = (float*)d_out;

    k_conv    <<<dim3(16, 4, 4), 256>>>(x, conv_w, conv_b, bn_g, bn_b, bn_mean, bn_var);
    k_gemm_xz <<<dim3(4, 128), 256>>>(in_w);
    k_cproj   <<<512, 256>>>(conv1d_w, conv1d_b, xproj_w, dtproj_w, dtproj_b, Dp);
    k_scan1   <<<dim3(32, NC, 4), 128>>>(A_log);
    k_scan2   <<<128, 128>>>();
    k_scan3   <<<dim3(32, NC, 4), 128>>>(A_log);
    k_gemm_out<<<128, 256>>>(out_w, out);
}